// round 2
// baseline (speedup 1.0000x reference)
#include <cuda_runtime.h>
#include <math.h>

#define NRAYS   10000
#define NSTEPS  768
#define Zn      32
#define Yn      512
#define Xn      512
#define WPB     8                       // warps (rays) per block
#define NBLK    ((NRAYS + WPB - 1) / WPB)   // 1250

// Per-block partial sums: [l1, l2, absrel] per block. Written by every block
// each launch before the reducer reads them -> no init needed.
__device__ float g_partials[NBLK * 3];

__global__ void __launch_bounds__(WPB * 32)
ray_march_kernel(const float* __restrict__ grid,     // [5,32,512,512] (T,Z,Y,X)
                 const float* __restrict__ origin,   // [5,3]
                 const float* __restrict__ pts,      // [NRAYS,3]
                 const int*   __restrict__ tindex)   // [NRAYS]
{
    const int warp = threadIdx.x >> 5;
    const int lane = threadIdx.x & 31;
    const int ray  = blockIdx.x * WPB + warp;   // grid sized exactly: always < NRAYS

    // --- per-ray setup (all lanes redundantly) ---
    const int ti = tindex[ray];
    const float ox = (origin[ti * 3 + 0] + 51.2f) / 0.2f;
    const float oy = (origin[ti * 3 + 1] + 51.2f) / 0.2f;
    const float oz = (origin[ti * 3 + 2] + 3.2f)  / 0.2f;
    const float px = (pts[ray * 3 + 0] + 51.2f) / 0.2f;
    const float py = (pts[ray * 3 + 1] + 51.2f) / 0.2f;
    const float pz = (pts[ray * 3 + 2] + 3.2f)  / 0.2f;

    const float dx = px - ox, dy = py - oy, dz = pz - oz;
    const float gt = sqrtf(dx * dx + dy * dy + dz * dz);
    const float inv = 1.0f / fmaxf(gt, 1e-6f);
    const float ux = dx * inv, uy = dy * inv, uz = dz * inv;

    const float* __restrict__ slice = grid + (size_t)ti * (Zn * Yn * Xn);

    float cum  = 0.0f;   // running sum of tau over all prior steps
    float pred = 0.0f;   // running sum of w * t

    for (int base = 0; base < NSTEPS; base += 32) {
        const float t = (float)(base + lane) + 0.5f;
        const float x = ox + ux * t;
        const float y = oy + uy * t;
        const float z = oz + uz * t;
        const int ix = (int)floorf(x);
        const int iy = (int)floorf(y);
        const int iz = (int)floorf(z);
        const bool inb = (ix >= 0) & (ix < Xn) & (iy >= 0) & (iy < Yn)
                       & (iz >= 0) & (iz < Zn);

        float tau = 0.0f;
        if (inb)
            tau = fmaxf(__ldg(&slice[((iz * Yn) + iy) * Xn + ix]), 0.0f);

        // inclusive warp scan of tau (ascending-t order)
        float cs = tau;
        #pragma unroll
        for (int off = 1; off < 32; off <<= 1) {
            float v = __shfl_up_sync(0xffffffffu, cs, off);
            if (lane >= off) cs += v;
        }

        const float cum_before = cum + (cs - tau);
        const float trans = __expf(-cum_before);
        const float w = trans * (1.0f - __expf(-tau));
        float c = w * t;

        // butterfly reduce: every lane gets the block's sum of w*t
        #pragma unroll
        for (int off = 16; off; off >>= 1)
            c += __shfl_xor_sync(0xffffffffu, c, off);
        pred += c;

        cum += __shfl_sync(0xffffffffu, cs, 31);   // total tau this block

        const unsigned bal = __ballot_sync(0xffffffffu, inb);
        // Exit when: last lane left the box (convex => no re-entry, all later
        // tau == 0, exact) OR transmittance < 1e-12 (error bound << 1e-3).
        if (!((bal >> 31) & 1u) || cum > 28.0f) break;
    }

    // --- per-ray loss terms ---
    const float predm = pred * 0.2f;
    const float gtm   = gt * 0.2f;          // always >= 0 -> valid, count = NRAYS
    const float diff  = gtm - predm;
    const float l1 = fabsf(diff);
    const float l2 = diff * diff * 0.5f;
    const float ar = fabsf(diff) / fmaxf(gtm, 1e-6f);

    __shared__ float s1[WPB], s2[WPB], s3[WPB];
    if (lane == 0) { s1[warp] = l1; s2[warp] = l2; s3[warp] = ar; }
    __syncthreads();
    if (threadIdx.x == 0) {
        float a = 0.f, b = 0.f, cc = 0.f;
        #pragma unroll
        for (int i = 0; i < WPB; i++) { a += s1[i]; b += s2[i]; cc += s3[i]; }
        g_partials[blockIdx.x * 3 + 0] = a;
        g_partials[blockIdx.x * 3 + 1] = b;
        g_partials[blockIdx.x * 3 + 2] = cc;
    }
}

__global__ void __launch_bounds__(256)
reduce_kernel(float* __restrict__ out)
{
    __shared__ float sh[3 * 256];
    float a = 0.f, b = 0.f, c = 0.f;
    for (int i = threadIdx.x; i < NBLK; i += 256) {
        a += g_partials[i * 3 + 0];
        b += g_partials[i * 3 + 1];
        c += g_partials[i * 3 + 2];
    }
    sh[threadIdx.x]       = a;
    sh[256 + threadIdx.x] = b;
    sh[512 + threadIdx.x] = c;
    __syncthreads();
    if (threadIdx.x == 0) {
        float ta = 0.f, tb = 0.f, tc = 0.f;
        for (int i = 0; i < 256; i++) {
            ta += sh[i]; tb += sh[256 + i]; tc += sh[512 + i];
        }
        const float cnt = (float)NRAYS;
        out[0] = ta / cnt;
        out[1] = tb / cnt;
        out[2] = tc / cnt;
    }
}

extern "C" void kernel_launch(void* const* d_in, const int* in_sizes, int n_in,
                              void* d_out, int out_size)
{
    const float* grid   = (const float*)d_in[0];   // (1,5,32,512,512) f32
    const float* origin = (const float*)d_in[1];   // (1,5,3) f32
    const float* pts    = (const float*)d_in[2];   // (1,10000,3) f32
    const int*   tidx   = (const int*)d_in[3];     // (1,10000) i32
    float* out = (float*)d_out;                    // 3 floats

    ray_march_kernel<<<NBLK, WPB * 32>>>(grid, origin, pts, tidx);
    reduce_kernel<<<1, 256>>>(out);
}

// round 4
// speedup vs baseline: 1.0886x; 1.0886x over previous
#include <cuda_runtime.h>
#include <math.h>

#define NRAYS   10000
#define NSTEPS  768
#define Zn      32
#define Yn      512
#define Xn      512
#define WPB     8                        // warps (rays) per block
#define NBLK    ((NRAYS + WPB - 1) / WPB)    // 1250

// Per-block partial sums [l1, l2, absrel]. Every block writes its slot each
// launch before any reader -> no init needed.
__device__ float    g_partials[NBLK * 3];
__device__ unsigned g_count = 0;         // reset by the last block each launch

__global__ void __launch_bounds__(WPB * 32)
ray_march_kernel(const float* __restrict__ grid,     // [5,32,512,512] (T,Z,Y,X)
                 const float* __restrict__ origin,   // [5,3]
                 const float* __restrict__ pts,      // [NRAYS,3]
                 const int*   __restrict__ tindex,   // [NRAYS]
                 float*       __restrict__ out)      // [3]
{
    const int warp = threadIdx.x >> 5;
    const int lane = threadIdx.x & 31;
    const int ray  = blockIdx.x * WPB + warp;   // grid sized exactly: always < NRAYS

    // --- per-ray setup (all lanes redundantly) ---
    const int ti = tindex[ray];
    const float ox = (origin[ti * 3 + 0] + 51.2f) / 0.2f;
    const float oy = (origin[ti * 3 + 1] + 51.2f) / 0.2f;
    const float oz = (origin[ti * 3 + 2] + 3.2f)  / 0.2f;
    const float px = (pts[ray * 3 + 0] + 51.2f) / 0.2f;
    const float py = (pts[ray * 3 + 1] + 51.2f) / 0.2f;
    const float pz = (pts[ray * 3 + 2] + 3.2f)  / 0.2f;

    const float dx = px - ox, dy = py - oy, dz = pz - oz;
    const float gt = sqrtf(dx * dx + dy * dy + dz * dz);
    const float inv = 1.0f / fmaxf(gt, 1e-6f);
    const float ux = dx * inv, uy = dy * inv, uz = dz * inv;

    const float* __restrict__ slice = grid + (size_t)ti * (Zn * Yn * Xn);

    float cum  = 0.0f;   // running sum of tau over all prior steps
    float pred = 0.0f;   // running sum of w * t

    for (int base = 0; base < NSTEPS; base += 32) {
        const float t = (float)(base + lane) + 0.5f;
        const int ix = (int)floorf(ox + ux * t);
        const int iy = (int)floorf(oy + uy * t);
        const int iz = (int)floorf(oz + uz * t);
        const bool inb = (ix >= 0) & (ix < Xn) & (iy >= 0) & (iy < Yn)
                       & (iz >= 0) & (iz < Zn);

        float tau = 0.0f;
        if (inb)
            tau = fmaxf(__ldg(&slice[((iz * Yn) + iy) * Xn + ix]), 0.0f);

        // inclusive warp scan of tau (ascending-t order)
        float cs = tau;
        #pragma unroll
        for (int off = 1; off < 32; off <<= 1) {
            float v = __shfl_up_sync(0xffffffffu, cs, off);
            if (lane >= off) cs += v;
        }

        const float cum_before = cum + (cs - tau);
        const float trans = __expf(-cum_before);
        const float w = trans * (1.0f - __expf(-tau));
        float c = w * t;

        // butterfly reduce: every lane gets this chunk's sum of w*t
        #pragma unroll
        for (int off = 16; off; off >>= 1)
            c += __shfl_xor_sync(0xffffffffu, c, off);
        pred += c;

        cum += __shfl_sync(0xffffffffu, cs, 31);   // total tau this chunk

        const unsigned bal = __ballot_sync(0xffffffffu, inb);
        // Exit when: last lane left the box (convex => no re-entry, all later
        // tau == 0, exact) OR transmittance < 1e-12 (error << 1e-3 budget).
        if (!((bal >> 31) & 1u) || cum > 28.0f) break;
    }

    // --- per-ray loss terms ---
    const float predm = pred * 0.2f;
    const float gtm   = gt * 0.2f;          // always >= 0 -> valid, count = NRAYS
    const float diff  = gtm - predm;
    float l1 = fabsf(diff);
    float l2 = diff * diff * 0.5f;
    float ar = fabsf(diff) / fmaxf(gtm, 1e-6f);

    // Per-block reduction: warps hold scalars in lane 0; use smem across warps.
    __shared__ float s1[WPB], s2[WPB], s3[WPB];
    if (lane == 0) { s1[warp] = l1; s2[warp] = l2; s3[warp] = ar; }
    __syncthreads();
    if (threadIdx.x < 32) {
        float a = (lane < WPB) ? s1[lane] : 0.f;
        float b = (lane < WPB) ? s2[lane] : 0.f;
        float d = (lane < WPB) ? s3[lane] : 0.f;
        #pragma unroll
        for (int off = WPB >> 1; off; off >>= 1) {
            a += __shfl_xor_sync(0xffffffffu, a, off);
            b += __shfl_xor_sync(0xffffffffu, b, off);
            d += __shfl_xor_sync(0xffffffffu, d, off);
        }
        if (lane == 0) {
            g_partials[blockIdx.x * 3 + 0] = a;
            g_partials[blockIdx.x * 3 + 1] = b;
            g_partials[blockIdx.x * 3 + 2] = d;
        }
    }

    // --- last-block final reduction (threadfence reduction pattern) ---
    __shared__ unsigned s_isLast;
    __threadfence();                     // publish partials before counter bump
    if (threadIdx.x == 0)
        s_isLast = (atomicAdd(&g_count, 1u) == (unsigned)(NBLK - 1));
    __syncthreads();

    if (s_isLast) {
        // Fixed-order strided sums: deterministic regardless of which block runs this.
        float a = 0.f, b = 0.f, d = 0.f;
        for (int i = threadIdx.x; i < NBLK; i += WPB * 32) {
            a += g_partials[i * 3 + 0];
            b += g_partials[i * 3 + 1];
            d += g_partials[i * 3 + 2];
        }
        #pragma unroll
        for (int off = 16; off; off >>= 1) {
            a += __shfl_xor_sync(0xffffffffu, a, off);
            b += __shfl_xor_sync(0xffffffffu, b, off);
            d += __shfl_xor_sync(0xffffffffu, d, off);
        }
        if (lane == 0) { s1[warp] = a; s2[warp] = b; s3[warp] = d; }
        __syncthreads();
        if (threadIdx.x == 0) {
            float ta = 0.f, tb = 0.f, td = 0.f;
            #pragma unroll
            for (int i = 0; i < WPB; i++) { ta += s1[i]; tb += s2[i]; td += s3[i]; }
            const float cnt = (float)NRAYS;
            out[0] = ta / cnt;
            out[1] = tb / cnt;
            out[2] = td / cnt;
            g_count = 0;                 // reset for next graph replay
        }
    }
}

extern "C" void kernel_launch(void* const* d_in, const int* in_sizes, int n_in,
                              void* d_out, int out_size)
{
    const float* grid   = (const float*)d_in[0];   // (1,5,32,512,512) f32
    const float* origin = (const float*)d_in[1];   // (1,5,3) f32
    const float* pts    = (const float*)d_in[2];   // (1,10000,3) f32
    const int*   tidx   = (const int*)d_in[3];     // (1,10000) i32
    float* out = (float*)d_out;                    // 3 floats

    ray_march_kernel<<<NBLK, WPB * 32>>>(grid, origin, pts, tidx, out);
}